// round 4
// baseline (speedup 1.0000x reference)
#include <cuda_runtime.h>
#include <cstdint>

// Problem constants
#define B_      8
#define C_      256
#define H_      128
#define W_      128
#define HW_     (H_ * W_)          // 16384
#define P2_     64                 // 8x8 patch
#define NPATCH_ 2048               // B * 16 * 16
#define GROUPS_ 32
#define CPG_    8                  // channels per group
#define EPS_    1e-5f

// ---------------------------------------------------------------------------
// Scratch (no cudaMalloc allowed): conv outputs + groupnorm stats
// ---------------------------------------------------------------------------
__device__ float  g_Yq[(size_t)B_ * C_ * HW_];     // conv_q output (pre-GN)
__device__ float  g_Yk[(size_t)B_ * C_ * HW_];     // conv_k output (pre-GN)
__device__ float2 g_stats[2][B_][GROUPS_];         // (mean, rstd) per tensor/b/group

// ---------------------------------------------------------------------------
// Kernel 1: 1x1 conv as GEMM.  Y[b][o][s] = sum_c W[o][c] * X[b][c][s]
// Tile: 128 (o) x 64 (s), K-chunk 16. 256 threads, 8x4 outputs per thread.
// which==0 -> g_Yq, which==1 -> g_Yk
// ---------------------------------------------------------------------------
__global__ __launch_bounds__(256) void conv1x1_kernel(
    const float* __restrict__ X, const float* __restrict__ Wm, int which)
{
    __shared__ float xs[16][64];     // [k][s]
    __shared__ float ws[16][129];    // [k][o], padded vs bank conflicts

    float* __restrict__ Y = which ? g_Yk : g_Yq;

    const int tid = threadIdx.x;
    const int tx = tid & 15;         // s sub-index (x4)
    const int ty = tid >> 4;         // o sub-index (stride 16)
    const int s0 = blockIdx.x * 64;
    const int o0 = blockIdx.y * 128;
    const int b  = blockIdx.z;

    const float* Xb = X + (size_t)b * C_ * HW_;

    float acc[8][4];
#pragma unroll
    for (int m = 0; m < 8; m++)
#pragma unroll
        for (int u = 0; u < 4; u++) acc[m][u] = 0.f;

    const int xr  = tid >> 4;        // 16 rows of X tile
    const int xc4 = tid & 15;        // 16 float4 columns
    const int wo  = tid >> 1;        // 128 o rows of W tile
    const int wk  = (tid & 1) * 8;   // 2 float4s along k

    for (int c0 = 0; c0 < C_; c0 += 16) {
        float4 xv  = *reinterpret_cast<const float4*>(Xb + (size_t)(c0 + xr) * HW_ + s0 + xc4 * 4);
        float4 wv0 = *reinterpret_cast<const float4*>(Wm + (size_t)(o0 + wo) * C_ + c0 + wk);
        float4 wv1 = *reinterpret_cast<const float4*>(Wm + (size_t)(o0 + wo) * C_ + c0 + wk + 4);

        reinterpret_cast<float4*>(&xs[xr][0])[xc4] = xv;
        ws[wk + 0][wo] = wv0.x; ws[wk + 1][wo] = wv0.y;
        ws[wk + 2][wo] = wv0.z; ws[wk + 3][wo] = wv0.w;
        ws[wk + 4][wo] = wv1.x; ws[wk + 5][wo] = wv1.y;
        ws[wk + 6][wo] = wv1.z; ws[wk + 7][wo] = wv1.w;
        __syncthreads();

#pragma unroll
        for (int k = 0; k < 16; k++) {
            float4 x4 = reinterpret_cast<float4*>(&xs[k][0])[tx];
            float wreg[8];
#pragma unroll
            for (int m = 0; m < 8; m++) wreg[m] = ws[k][ty + 16 * m];
#pragma unroll
            for (int m = 0; m < 8; m++) {
                acc[m][0] += wreg[m] * x4.x;
                acc[m][1] += wreg[m] * x4.y;
                acc[m][2] += wreg[m] * x4.z;
                acc[m][3] += wreg[m] * x4.w;
            }
        }
        __syncthreads();
    }

    float* Yb = Y + ((size_t)b * C_ + o0) * HW_ + s0;
#pragma unroll
    for (int m = 0; m < 8; m++) {
        float4 v = make_float4(acc[m][0], acc[m][1], acc[m][2], acc[m][3]);
        *reinterpret_cast<float4*>(Yb + (size_t)(ty + 16 * m) * HW_ + tx * 4) = v;
    }
}

// ---------------------------------------------------------------------------
// Kernel 2: GroupNorm statistics. One CTA per (tensor, b, group).
// A group's data is a contiguous 8*HW block. Deterministic tree reduction.
// ---------------------------------------------------------------------------
__global__ __launch_bounds__(256) void gn_stats_kernel()
{
    const int id = blockIdx.x;            // 0..511
    const int t  = id >> 8;               // 0 = q, 1 = k
    const int b  = (id >> 5) & 7;
    const int g  = id & 31;

    const float* base = (t == 0 ? g_Yq : g_Yk) + ((size_t)(b * C_ + g * CPG_)) * HW_;
    const float4* p4 = reinterpret_cast<const float4*>(base);
    const int n4 = CPG_ * HW_ / 4;        // 32768 float4s

    float s = 0.f, ss = 0.f;
    for (int i = threadIdx.x; i < n4; i += 256) {
        float4 v = p4[i];
        s  += v.x + v.y + v.z + v.w;
        ss += v.x * v.x + v.y * v.y + v.z * v.z + v.w * v.w;
    }

    __shared__ float rs[256], rss[256];
    rs[threadIdx.x] = s; rss[threadIdx.x] = ss;
    __syncthreads();
    for (int st = 128; st > 0; st >>= 1) {
        if (threadIdx.x < st) {
            rs[threadIdx.x]  += rs[threadIdx.x + st];
            rss[threadIdx.x] += rss[threadIdx.x + st];
        }
        __syncthreads();
    }
    if (threadIdx.x == 0) {
        const float inv = 1.0f / (float)(CPG_ * HW_);
        float mu  = rs[0] * inv;
        float var = rss[0] * inv - mu * mu;
        g_stats[t][b][g] = make_float2(mu, rsqrtf(var + EPS_));
    }
}

// ---------------------------------------------------------------------------
// Kernel 3: per-patch attention, fully in SMEM. One CTA per patch (2048 CTAs).
//   load+normalize q,k tiles -> S = q^T k / 16 -> row softmax -> O = A k^T
//   -> stage O in smem -> coalesced writeback with residual.
// SMEM: qs[256][65] + ks[256][65] + smA[64][65]  = 149760 B
// ---------------------------------------------------------------------------
#define ATTN_SMEM ((256 * 65 * 2 + 64 * 65) * 4)

__global__ __launch_bounds__(256, 1) void attn_kernel(
    const float* __restrict__ xlow,
    const float* __restrict__ gq, const float* __restrict__ bq,
    const float* __restrict__ gk, const float* __restrict__ bk,
    float* __restrict__ out)
{
    extern __shared__ float sm[];
    float* qs  = sm;                 // [256][65]  q (normalized), later reused for O
    float* ks  = sm + 256 * 65;      // [256][65]  k (normalized)
    float* smA = ks + 256 * 65;      // [64][65]   scores / attention weights

    const int n  = blockIdx.x;
    const int b  = n >> 8;
    const int ph = (n >> 4) & 15;
    const int pw = n & 15;
    const int tid = threadIdx.x;

    const size_t pbase = (size_t)b * C_ * HW_ + (size_t)(ph * 8) * W_ + pw * 8;

    // --- load + normalize patch tiles (32B-sector-aligned global reads) ---
    for (int idx = tid; idx < C_ * P2_; idx += 256) {
        int c = idx >> 6, p = idx & 63;
        int i = p >> 3,  j = p & 7;
        size_t off = pbase + (size_t)c * HW_ + i * W_ + j;
        float2 stq = g_stats[0][b][c >> 3];
        float2 stk = g_stats[1][b][c >> 3];
        qs[c * 65 + p] = (g_Yq[off] - stq.x) * stq.y * __ldg(gq + c) + __ldg(bq + c);
        ks[c * 65 + p] = (g_Yk[off] - stk.x) * stk.y * __ldg(gk + c) + __ldg(bk + c);
    }
    __syncthreads();

    const int tx = tid & 15;   // col sub-index
    const int ty = tid >> 4;   // row sub-index

    // --- S[p][p'] = sum_c q[c][p] k[c][p'] * (1/16) ---
    {
        float sacc[4][4];
#pragma unroll
        for (int m = 0; m < 4; m++)
#pragma unroll
            for (int u = 0; u < 4; u++) sacc[m][u] = 0.f;

#pragma unroll 4
        for (int c = 0; c < C_; c++) {
            float qv[4], kv[4];
#pragma unroll
            for (int m = 0; m < 4; m++) qv[m] = qs[c * 65 + ty + 16 * m];
#pragma unroll
            for (int u = 0; u < 4; u++) kv[u] = ks[c * 65 + tx + 16 * u];
#pragma unroll
            for (int m = 0; m < 4; m++)
#pragma unroll
                for (int u = 0; u < 4; u++) sacc[m][u] += qv[m] * kv[u];
        }
#pragma unroll
        for (int m = 0; m < 4; m++)
#pragma unroll
            for (int u = 0; u < 4; u++)
                smA[(ty + 16 * m) * 65 + tx + 16 * u] = sacc[m][u] * 0.0625f;
    }
    __syncthreads();

    // --- row softmax (64 rows, one thread each) ---
    if (tid < 64) {
        float* row = smA + tid * 65;
        float mx = -1e30f;
#pragma unroll 8
        for (int j = 0; j < 64; j++) mx = fmaxf(mx, row[j]);
        float s = 0.f;
#pragma unroll 8
        for (int j = 0; j < 64; j++) { float e = __expf(row[j] - mx); row[j] = e; s += e; }
        float inv = 1.0f / s;
#pragma unroll 8
        for (int j = 0; j < 64; j++) row[j] *= inv;
    }
    __syncthreads();

    // --- O[p][c] = sum_p' A[p][p'] k[c][p'] ; stage into qs[c][p] ---
    {
        float oacc[4][16];
#pragma unroll
        for (int m = 0; m < 4; m++)
#pragma unroll
            for (int u = 0; u < 16; u++) oacc[m][u] = 0.f;

#pragma unroll 2
        for (int pp = 0; pp < 64; pp++) {
            float av[4];
#pragma unroll
            for (int m = 0; m < 4; m++) av[m] = smA[(ty + 16 * m) * 65 + pp];
            float kv[16];
#pragma unroll
            for (int u = 0; u < 16; u++) kv[u] = ks[(tx + 16 * u) * 65 + pp];
#pragma unroll
            for (int m = 0; m < 4; m++)
#pragma unroll
                for (int u = 0; u < 16; u++) oacc[m][u] += av[m] * kv[u];
        }
#pragma unroll
        for (int m = 0; m < 4; m++)
#pragma unroll
            for (int u = 0; u < 16; u++)
                qs[(tx + 16 * u) * 65 + (ty + 16 * m)] = oacc[m][u];
    }
    __syncthreads();

    // --- coalesced writeback with residual ---
    for (int idx = tid; idx < C_ * P2_; idx += 256) {
        int c = idx >> 6, p = idx & 63;
        int i = p >> 3,  j = p & 7;
        size_t off = pbase + (size_t)c * HW_ + i * W_ + j;
        out[off] = qs[c * 65 + p] + xlow[off];
    }
}

// ---------------------------------------------------------------------------
// Launch
// ---------------------------------------------------------------------------
extern "C" void kernel_launch(void* const* d_in, const int* in_sizes, int n_in,
                              void* d_out, int out_size)
{
    const float* x_low  = (const float*)d_in[0];
    const float* x_high = (const float*)d_in[1];
    const float* Wq     = (const float*)d_in[2];
    const float* gq     = (const float*)d_in[3];
    const float* bq     = (const float*)d_in[4];
    const float* Wk     = (const float*)d_in[5];
    const float* gk     = (const float*)d_in[6];
    const float* bk     = (const float*)d_in[7];
    float* out = (float*)d_out;

    cudaFuncSetAttribute(attn_kernel, cudaFuncAttributeMaxDynamicSharedMemorySize, ATTN_SMEM);

    dim3 cgrid(HW_ / 64, C_ / 128, B_);   // (256, 2, 8)
    conv1x1_kernel<<<cgrid, 256>>>(x_low,  Wq, 0);
    conv1x1_kernel<<<cgrid, 256>>>(x_high, Wk, 1);
    gn_stats_kernel<<<2 * B_ * GROUPS_, 256>>>();
    attn_kernel<<<NPATCH_, 256, ATTN_SMEM>>>(x_low, gq, bq, gk, bk, out);
}

// round 5
// speedup vs baseline: 1.3976x; 1.3976x over previous
#include <cuda_runtime.h>
#include <cstdint>

#define B_      8
#define C_      256
#define H_      128
#define W_      128
#define HW_     (H_ * W_)
#define GROUPS_ 32
#define CPG_    8
#define EPS_    1e-5f
#define AST     68                 // attn smem row stride (floats), 16B-aligned, conflict-free

typedef unsigned long long u64;

// ---------------------------------------------------------------------------
// Scratch
// ---------------------------------------------------------------------------
__device__ float  g_Yq[(size_t)B_ * C_ * HW_];
__device__ float  g_Yk[(size_t)B_ * C_ * HW_];
__device__ float  g_Wt[2][C_ * C_];            // W transposed: [c][o]
__device__ float2 g_stats[2][B_][GROUPS_];

// ---------------------------------------------------------------------------
// Packed fp32x2 helpers (sm_103a FFMA2 path — PTX-only, full fp32 precision)
// ---------------------------------------------------------------------------
#define FMA2(acc, a, b) asm("fma.rn.f32x2 %0, %1, %2, %0;" : "+l"(acc) : "l"(a), "l"(b))

__device__ __forceinline__ u64 bcast2(float f) {
    u64 d; unsigned u = __float_as_uint(f);
    asm("mov.b64 %0, {%1, %1};" : "=l"(d) : "r"(u));
    return d;
}
__device__ __forceinline__ float2 unpack2(u64 p) {
    unsigned a, b;
    asm("mov.b64 {%0, %1}, %2;" : "=r"(a), "=r"(b) : "l"(p));
    return make_float2(__uint_as_float(a), __uint_as_float(b));
}

// ---------------------------------------------------------------------------
// Kernel 0: transpose W (256x256) once so conv smem fill is conflict-free
// ---------------------------------------------------------------------------
__global__ __launch_bounds__(256) void wtrans_kernel(
    const float* __restrict__ Wq, const float* __restrict__ Wk)
{
    __shared__ float t[32][33];
    const float* Wm = blockIdx.z ? Wk : Wq;
    float* T = g_Wt[blockIdx.z];
    const int bx = blockIdx.x * 32, by = blockIdx.y * 32;
    const int tx = threadIdx.x, ty = threadIdx.y;   // 32 x 8
#pragma unroll
    for (int r = 0; r < 32; r += 8)
        t[ty + r][tx] = Wm[(size_t)(by + ty + r) * C_ + bx + tx];
    __syncthreads();
#pragma unroll
    for (int r = 0; r < 32; r += 8)
        T[(size_t)(bx + ty + r) * C_ + by + tx] = t[tx][ty + r];
}

// ---------------------------------------------------------------------------
// Kernel 1: 1x1 conv as GEMM, FFMA2 path.
// Tile 128(o) x 128(s), K-chunk 16, double-buffered smem, 256 thr, 8x8/thread.
// ---------------------------------------------------------------------------
__global__ __launch_bounds__(256, 2) void conv1x1_kernel(
    const float* __restrict__ X, int which)
{
    __shared__ __align__(16) float xs[2][16][128];   // [buf][k][s]
    __shared__ __align__(16) float ws[2][16][128];   // [buf][k][o]

    float* __restrict__ Y = which ? g_Yk : g_Yq;
    const float* __restrict__ Wt = g_Wt[which];

    const int tid = threadIdx.x;
    const int tx = tid & 15;          // s groups: {4tx..4tx+3, 64+4tx..+3}
    const int ty = tid >> 4;          // o groups: {4ty..4ty+3, 64+4ty..+3}
    const int s0 = blockIdx.x * 128;
    const int o0 = blockIdx.y * 128;
    const int b  = blockIdx.z;
    const float* Xb = X + (size_t)b * C_ * HW_;

    u64 acc[8][4];
#pragma unroll
    for (int m = 0; m < 8; m++)
#pragma unroll
        for (int u = 0; u < 4; u++) acc[m][u] = 0ull;

    const int lr = ty;                // loader row (16), f4 cols lc & lc+16
    const int lc = tx;

    float4 xg0, xg1, wg0, wg1;
    {   // chunk 0
        const float* xp = Xb + (size_t)lr * HW_ + s0;
        xg0 = *(const float4*)(xp + lc * 4);
        xg1 = *(const float4*)(xp + 64 + lc * 4);
        const float* wp = Wt + (size_t)lr * C_ + o0;
        wg0 = *(const float4*)(wp + lc * 4);
        wg1 = *(const float4*)(wp + 64 + lc * 4);
    }
    *(float4*)&xs[0][lr][lc * 4]      = xg0;
    *(float4*)&xs[0][lr][64 + lc * 4] = xg1;
    *(float4*)&ws[0][lr][lc * 4]      = wg0;
    *(float4*)&ws[0][lr][64 + lc * 4] = wg1;
    __syncthreads();

    for (int ch = 0; ch < 16; ch++) {
        const int buf = ch & 1;
        if (ch < 15) {
            const int c0 = (ch + 1) * 16;
            const float* xp = Xb + (size_t)(c0 + lr) * HW_ + s0;
            xg0 = *(const float4*)(xp + lc * 4);
            xg1 = *(const float4*)(xp + 64 + lc * 4);
            const float* wp = Wt + (size_t)(c0 + lr) * C_ + o0;
            wg0 = *(const float4*)(wp + lc * 4);
            wg1 = *(const float4*)(wp + 64 + lc * 4);
        }
#pragma unroll
        for (int k = 0; k < 16; k++) {
            ulonglong2 xa = *(const ulonglong2*)&xs[buf][k][4 * tx];
            ulonglong2 xb = *(const ulonglong2*)&xs[buf][k][64 + 4 * tx];
            float4 wa = *(const float4*)&ws[buf][k][4 * ty];
            float4 wb = *(const float4*)&ws[buf][k][64 + 4 * ty];
            u64 wp2[8];
            wp2[0] = bcast2(wa.x); wp2[1] = bcast2(wa.y);
            wp2[2] = bcast2(wa.z); wp2[3] = bcast2(wa.w);
            wp2[4] = bcast2(wb.x); wp2[5] = bcast2(wb.y);
            wp2[6] = bcast2(wb.z); wp2[7] = bcast2(wb.w);
#pragma unroll
            for (int m = 0; m < 8; m++) {
                FMA2(acc[m][0], wp2[m], xa.x);
                FMA2(acc[m][1], wp2[m], xa.y);
                FMA2(acc[m][2], wp2[m], xb.x);
                FMA2(acc[m][3], wp2[m], xb.y);
            }
        }
        if (ch < 15) {
            const int nb = buf ^ 1;
            *(float4*)&xs[nb][lr][lc * 4]      = xg0;
            *(float4*)&xs[nb][lr][64 + lc * 4] = xg1;
            *(float4*)&ws[nb][lr][lc * 4]      = wg0;
            *(float4*)&ws[nb][lr][64 + lc * 4] = wg1;
            __syncthreads();
        }
    }

    float* Yb = Y + ((size_t)b * C_ + o0) * HW_ + s0;
#pragma unroll
    for (int m = 0; m < 8; m++) {
        const int o = (m < 4) ? (4 * ty + m) : (64 + 4 * ty + (m - 4));
        float2 p0 = unpack2(acc[m][0]), p1 = unpack2(acc[m][1]);
        float2 p2 = unpack2(acc[m][2]), p3 = unpack2(acc[m][3]);
        *(float4*)(Yb + (size_t)o * HW_ + 4 * tx)      = make_float4(p0.x, p0.y, p1.x, p1.y);
        *(float4*)(Yb + (size_t)o * HW_ + 64 + 4 * tx) = make_float4(p2.x, p2.y, p3.x, p3.y);
    }
}

// ---------------------------------------------------------------------------
// Kernel 2: GroupNorm stats. One CTA per (tensor, b, group). 512 threads.
// ---------------------------------------------------------------------------
__global__ __launch_bounds__(512) void gn_stats_kernel()
{
    const int id = blockIdx.x;
    const int t  = id >> 8;
    const int b  = (id >> 5) & 7;
    const int g  = id & 31;

    const float* base = (t == 0 ? g_Yq : g_Yk) + ((size_t)(b * C_ + g * CPG_)) * HW_;
    const float4* p4 = reinterpret_cast<const float4*>(base);
    const int n4 = CPG_ * HW_ / 4;      // 32768

    float s = 0.f, ss = 0.f;
#pragma unroll 4
    for (int i = threadIdx.x; i < n4; i += 512) {
        float4 v = p4[i];
        s  += v.x + v.y + v.z + v.w;
        ss += v.x * v.x + v.y * v.y + v.z * v.z + v.w * v.w;
    }

    __shared__ float rs[512], rss[512];
    rs[threadIdx.x] = s; rss[threadIdx.x] = ss;
    __syncthreads();
    for (int st = 256; st > 0; st >>= 1) {
        if (threadIdx.x < st) {
            rs[threadIdx.x]  += rs[threadIdx.x + st];
            rss[threadIdx.x] += rss[threadIdx.x + st];
        }
        __syncthreads();
    }
    if (threadIdx.x == 0) {
        const float inv = 1.0f / (float)(CPG_ * HW_);
        float mu  = rs[0] * inv;
        float var = rss[0] * inv - mu * mu;
        g_stats[t][b][g] = make_float2(mu, rsqrtf(var + EPS_));
    }
}

// ---------------------------------------------------------------------------
// Kernel 3: per-patch attention, FFMA2 + conflict-free smem GEMMs.
// smem: qs[256][68] + ks[256][68] + 4 x A[64][68]  = 208896 B
// ---------------------------------------------------------------------------
#define ATTN_SMEM ((2 * 256 * AST + 4 * 64 * AST) * 4)

__global__ __launch_bounds__(256, 1) void attn_kernel(
    const float* __restrict__ xlow,
    const float* __restrict__ gq, const float* __restrict__ bq,
    const float* __restrict__ gk, const float* __restrict__ bk,
    float* __restrict__ out)
{
    extern __shared__ __align__(16) float sm[];
    float* qs  = sm;                       // [256][68] q; reused as O staging
    float* ks  = sm + 256 * AST;           // [256][68]
    float* smA = sm + 2 * 256 * AST;       // 4 x [64][68] partial S; [0] = final A

    const int n  = blockIdx.x;
    const int b  = n >> 8;
    const int ph = (n >> 4) & 15;
    const int pw = n & 15;
    const int tid = threadIdx.x;
    const size_t pbase = (size_t)b * C_ * HW_ + (size_t)(ph * 8) * W_ + pw * 8;

    // --- load + normalize (float4, 32B-sector-aligned) ---
    for (int u = tid; u < C_ * 16; u += 256) {
        const int c = u >> 4, i = (u >> 1) & 7, jh = u & 1;
        const size_t off = pbase + (size_t)c * HW_ + i * W_ + jh * 4;
        const float2 stq = g_stats[0][b][c >> 3];
        const float2 stk = g_stats[1][b][c >> 3];
        const float aq = stq.y * gq[c], cq = bq[c] - stq.x * aq;
        const float ak = stk.y * gk[c], ck = bk[c] - stk.x * ak;
        const float4 vq = *(const float4*)(g_Yq + off);
        const float4 vk = *(const float4*)(g_Yk + off);
        const int p = i * 8 + jh * 4;
        *(float4*)&qs[c * AST + p] = make_float4(vq.x*aq+cq, vq.y*aq+cq, vq.z*aq+cq, vq.w*aq+cq);
        *(float4*)&ks[c * AST + p] = make_float4(vk.x*ak+ck, vk.y*ak+ck, vk.z*ak+ck, vk.w*ak+ck);
    }
    __syncthreads();

    // --- S partial GEMM, c-split-4: quarter q handles c in [64q, 64q+64) ---
    {
        const int quarter = tid >> 6, tq = tid & 63;
        const int rb = tq >> 3;            // rows 8rb..8rb+7 (contiguous)
        const int cb = tq & 7;             // cols {4cb..+3, 32+4cb..+3}
        float* Aq = smA + quarter * 64 * AST;

        u64 acc[8][4];
#pragma unroll
        for (int m = 0; m < 8; m++)
#pragma unroll
            for (int u = 0; u < 4; u++) acc[m][u] = 0ull;

        const int cbeg = quarter * 64;
        for (int c = cbeg; c < cbeg + 64; c++) {
            const float* qr = qs + c * AST + 8 * rb;
            float4 qa = *(const float4*)qr;
            float4 qb = *(const float4*)(qr + 4);
            ulonglong2 ka = *(const ulonglong2*)&ks[c * AST + 4 * cb];
            ulonglong2 kb = *(const ulonglong2*)&ks[c * AST + 32 + 4 * cb];
            u64 qp[8];
            qp[0] = bcast2(qa.x); qp[1] = bcast2(qa.y);
            qp[2] = bcast2(qa.z); qp[3] = bcast2(qa.w);
            qp[4] = bcast2(qb.x); qp[5] = bcast2(qb.y);
            qp[6] = bcast2(qb.z); qp[7] = bcast2(qb.w);
#pragma unroll
            for (int m = 0; m < 8; m++) {
                FMA2(acc[m][0], qp[m], ka.x);
                FMA2(acc[m][1], qp[m], ka.y);
                FMA2(acc[m][2], qp[m], kb.x);
                FMA2(acc[m][3], qp[m], kb.y);
            }
        }
#pragma unroll
        for (int m = 0; m < 8; m++) {
            *(ulonglong2*)&Aq[(8 * rb + m) * AST + 4 * cb]      = make_ulonglong2(acc[m][0], acc[m][1]);
            *(ulonglong2*)&Aq[(8 * rb + m) * AST + 32 + 4 * cb] = make_ulonglong2(acc[m][2], acc[m][3]);
        }
    }
    __syncthreads();

    // --- reduce 4 partials into smA[0], scale by 1/sqrt(C)=1/16 ---
    {
        float4* A4 = (float4*)smA;
        const int nf4 = 64 * AST / 4;      // 1088
        for (int f = tid; f < nf4; f += 256) {
            float4 a = A4[f], b1 = A4[f + nf4], c2 = A4[f + 2 * nf4], d = A4[f + 3 * nf4];
            A4[f] = make_float4((a.x + b1.x + c2.x + d.x) * 0.0625f,
                                (a.y + b1.y + c2.y + d.y) * 0.0625f,
                                (a.z + b1.z + c2.z + d.z) * 0.0625f,
                                (a.w + b1.w + c2.w + d.w) * 0.0625f);
        }
    }
    __syncthreads();

    // --- row softmax on smA[0] ---
    if (tid < 64) {
        float* row = smA + tid * AST;
        float mx = -1e30f;
#pragma unroll 8
        for (int j = 0; j < 64; j++) mx = fmaxf(mx, row[j]);
        float s = 0.f;
#pragma unroll 8
        for (int j = 0; j < 64; j++) { float e = __expf(row[j] - mx); row[j] = e; s += e; }
        float inv = 1.0f / s;
#pragma unroll 8
        for (int j = 0; j < 64; j++) row[j] *= inv;
    }
    __syncthreads();

    // --- O = A * k^T : 8p x 8c per thread, pp-pair FFMA2, no broadcasts ---
    {
        const int pg = tid & 7;            // p-set {pg+8j}
        const int cg = tid >> 3;           // c-set {cg+32j}
        u64 acc[8][8];
#pragma unroll
        for (int jp = 0; jp < 8; jp++)
#pragma unroll
            for (int jc = 0; jc < 8; jc++) acc[jp][jc] = 0ull;

        const float* A0 = smA;
        for (int pp = 0; pp < 64; pp += 4) {
            ulonglong2 ap[8];
#pragma unroll
            for (int j = 0; j < 8; j++)
                ap[j] = *(const ulonglong2*)&A0[(pg + 8 * j) * AST + pp];
#pragma unroll
            for (int jc = 0; jc < 8; jc++) {
                ulonglong2 kp = *(const ulonglong2*)&ks[(cg + 32 * jc) * AST + pp];
#pragma unroll
                for (int jp = 0; jp < 8; jp++) {
                    FMA2(acc[jp][jc], ap[jp].x, kp.x);
                    FMA2(acc[jp][jc], ap[jp].y, kp.y);
                }
            }
        }
        // stage O into qs[c][p] (qs no longer needed; all readers synced out)
#pragma unroll
        for (int jp = 0; jp < 8; jp++)
#pragma unroll
            for (int jc = 0; jc < 8; jc++) {
                float2 v = unpack2(acc[jp][jc]);
                qs[(cg + 32 * jc) * AST + (pg + 8 * jp)] = v.x + v.y;
            }
    }
    __syncthreads();

    // --- coalesced writeback with residual ---
    for (int u = tid; u < C_ * 16; u += 256) {
        const int c = u >> 4, i = (u >> 1) & 7, jh = u & 1;
        const size_t off = pbase + (size_t)c * HW_ + i * W_ + jh * 4;
        const int p = i * 8 + jh * 4;
        float4 o4 = *(const float4*)&qs[c * AST + p];
        float4 xl = *(const float4*)(xlow + off);
        *(float4*)(out + off) = make_float4(o4.x + xl.x, o4.y + xl.y, o4.z + xl.z, o4.w + xl.w);
    }
}

// ---------------------------------------------------------------------------
// Launch
// ---------------------------------------------------------------------------
extern "C" void kernel_launch(void* const* d_in, const int* in_sizes, int n_in,
                              void* d_out, int out_size)
{
    const float* x_low  = (const float*)d_in[0];
    const float* x_high = (const float*)d_in[1];
    const float* Wq     = (const float*)d_in[2];
    const float* gq     = (const float*)d_in[3];
    const float* bq     = (const float*)d_in[4];
    const float* Wk     = (const float*)d_in[5];
    const float* gk     = (const float*)d_in[6];
    const float* bk     = (const float*)d_in[7];
    float* out = (float*)d_out;

    cudaFuncSetAttribute(attn_kernel, cudaFuncAttributeMaxDynamicSharedMemorySize, ATTN_SMEM);

    dim3 tgrid(8, 8, 2);
    wtrans_kernel<<<tgrid, dim3(32, 8)>>>(Wq, Wk);

    dim3 cgrid(HW_ / 128, C_ / 128, B_);   // (128, 2, 8)
    conv1x1_kernel<<<cgrid, 256>>>(x_low,  0);
    conv1x1_kernel<<<cgrid, 256>>>(x_high, 1);
    gn_stats_kernel<<<2 * B_ * GROUPS_, 512>>>();
    attn_kernel<<<2048, 256, ATTN_SMEM>>>(x_low, gq, bq, gk, bk, out);
}